// round 10
// baseline (speedup 1.0000x reference)
#include <cuda_runtime.h>
#include <cuda_bf16.h>
#include <cstdint>

#define NTOK 8192
#define TOPK 2
#define NEXP 8
#define KDIM 512
#define NDIM 1024
#define MROWS (NTOK * TOPK)

#define TILE_M 128
#define TILE_N 128
#define CH_K   32
#define NUM_CH (KDIM / CH_K)
#define NTILES ((MROWS / TILE_M) * (NDIM / TILE_N))
#define NTN    (NDIM / TILE_N)
#define TBYTES (TILE_M * 128)
#define STAGE  (2 * TBYTES)
#define NSTAGE 3
#define SMEM_GEMM (NSTAGE * STAGE + 16)
#define GRID_GEMM 296
#define NTHREADS 128

__device__ __forceinline__ uint32_t smem_to_u32(const void* p) {
    uint32_t a;
    asm("{ .reg .u64 t; cvta.to.shared.u64 t, %1; cvt.u32.u64 %0, t; }"
        : "=r"(a) : "l"(p));
    return a;
}
__device__ __forceinline__ void cp_async16(uint32_t dst, const void* src) {
    asm volatile("cp.async.cg.shared.global [%0], [%1], 16;"
                 :: "r"(dst), "l"(src) : "memory");
}
__device__ __forceinline__ void cp_commit() {
    asm volatile("cp.async.commit_group;" ::: "memory");
}
template <int N>
__device__ __forceinline__ void cp_wait() {
    asm volatile("cp.async.wait_group %0;" :: "n"(N) : "memory");
}
__device__ __forceinline__ void ldm_x4(uint32_t* r, uint32_t addr) {
    asm volatile("ldmatrix.sync.aligned.m8n8.x4.shared.b16 {%0,%1,%2,%3}, [%4];"
                 : "=r"(r[0]), "=r"(r[1]), "=r"(r[2]), "=r"(r[3])
                 : "r"(addr));
}
__device__ __forceinline__ void mma_tf32(float* c, const uint32_t* a,
                                         const uint32_t* b) {
    asm volatile(
        "mma.sync.aligned.m16n8k8.row.col.f32.tf32.tf32.f32 "
        "{%0,%1,%2,%3}, {%4,%5,%6,%7}, {%8,%9}, {%0,%1,%2,%3};"
        : "+f"(c[0]), "+f"(c[1]), "+f"(c[2]), "+f"(c[3])
        : "r"(a[0]), "r"(a[1]), "r"(a[2]), "r"(a[3]), "r"(b[0]), "r"(b[1]));
}
__device__ __forceinline__ uint32_t f32_to_tf32(float f) {
    uint32_t o;
    asm("cvt.rna.tf32.f32 %0, %1;" : "=r"(o) : "f"(f));
    return o;
}
__device__ __forceinline__ void red_add_v2(float* gaddr, float x, float y) {
    asm volatile("red.global.add.v2.f32 [%0], {%1, %2};"
                 :: "l"(gaddr), "f"(x), "f"(y) : "memory");
}

__device__ uint4  d_a_t4[MROWS * KDIM / 4];           // tf32 [M,K]   (32 MB)
__device__ uint4  d_w_t4[NEXP * NDIM * KDIM / 4];     // tf32 [E,N,K] (32 MB)
__device__ float  d_rowscale[MROWS];
__device__ int    d_inv[MROWS];
__device__ int    d_tilectr;

// ---------------------------------------------------------------------------
// Kernel 1: convert input f32 -> tf32 (RN) + zero output surface
// ---------------------------------------------------------------------------
__global__ void k_split_input(const float4* __restrict__ in4,
                              float4* __restrict__ out4) {
    int i = blockIdx.x * blockDim.x + threadIdx.x;
    out4[2 * i]     = make_float4(0.f, 0.f, 0.f, 0.f);
    out4[2 * i + 1] = make_float4(0.f, 0.f, 0.f, 0.f);
    float4 v0 = in4[2 * i], v1 = in4[2 * i + 1];
    uint4 t0, t1;
    t0.x = f32_to_tf32(v0.x); t0.y = f32_to_tf32(v0.y);
    t0.z = f32_to_tf32(v0.z); t0.w = f32_to_tf32(v0.w);
    t1.x = f32_to_tf32(v1.x); t1.y = f32_to_tf32(v1.y);
    t1.z = f32_to_tf32(v1.z); t1.w = f32_to_tf32(v1.w);
    d_a_t4[2 * i]     = t0;
    d_a_t4[2 * i + 1] = t1;
}

// ---------------------------------------------------------------------------
// Kernel 2: weight [E,K,N] f32 -> [E,N,K] tf32 (32x32 SMEM transpose)
// ---------------------------------------------------------------------------
__global__ void k_split_weight(const float* __restrict__ w) {
    __shared__ float tile[32][33];
    int e = blockIdx.z;
    int k0 = blockIdx.x * 32;
    int n0 = blockIdx.y * 32;
    int tx = threadIdx.x, ty = threadIdx.y;
    #pragma unroll
    for (int i = 0; i < 4; i++) {
        int k = k0 + ty + 8 * i;
        tile[ty + 8 * i][tx] = w[((size_t)e * KDIM + k) * NDIM + n0 + tx];
    }
    __syncthreads();
    uint32_t* wt = (uint32_t*)d_w_t4;
    #pragma unroll
    for (int i = 0; i < 4; i++) {
        int n = n0 + ty + 8 * i;
        float v = tile[tx][ty + 8 * i];
        size_t o = ((size_t)e * NDIM + n) * KDIM + k0 + tx;
        wt[o] = f32_to_tf32(v);
    }
}

// ---------------------------------------------------------------------------
// Kernel 3: per-row epilogue scale + inverse scatter index + counter reset
// ---------------------------------------------------------------------------
__global__ void k_small(const int* __restrict__ splits,
                        const int* __restrict__ sidx,
                        const float* __restrict__ is,
                        const float* __restrict__ ws,
                        const float* __restrict__ ovs) {
    int m = blockIdx.x * blockDim.x + threadIdx.x;
    if (m == 0) d_tilectr = 0;
    if (m >= MROWS) return;
    int e = 0, cum = splits[0];
    while (m >= cum && e < NEXP - 1) { e++; cum += splits[e]; }
    d_rowscale[m] = is[0] * ws[e] * ovs[m];
    d_inv[sidx[m]] = m / TOPK;
}

__device__ __forceinline__ int expert_of(const int* splits, int m0) {
    int e = 0, cum = splits[0];
    while (m0 >= cum && e < NEXP - 1) { e++; cum += splits[e]; }
    return e;
}

// Issue half of a chunk's prefetch (reps [h*4, h*4+4) of 8).
__device__ __forceinline__ void load_chunk_half(uint32_t stagebase, int ch,
                                                int tid, int m0, int n0, int e,
                                                int h) {
    const char* aT = (const char*)d_a_t4;
    const char* bT = (const char*)d_w_t4;
    #pragma unroll
    for (int rep = h * 4; rep < h * 4 + 4; rep++) {
        int i = tid + rep * NTHREADS;
        int row = i >> 3, c = i & 7;
        uint32_t soff = row * 128 + ((c ^ (row & 7)) << 4);
        size_t ga = ((size_t)(m0 + row) * KDIM + ch * CH_K) * 4 + c * 16;
        size_t gb = (((size_t)e * NDIM + n0 + row) * KDIM + ch * CH_K) * 4 + c * 16;
        cp_async16(stagebase + soff, aT + ga);
        cp_async16(stagebase + TBYTES + soff, bT + gb);
    }
}

// ---------------------------------------------------------------------------
// Kernel 4: persistent grouped GEMM (single-pass tf32 mma m16n8k8, 64x64
// warp tiles, 3-stage cp.async ring rolling across tile boundaries, dynamic
// tile stealing, LDSM-first chunk body with interleaved prefetch, fused
// scale + scatter-reduce epilogue via red.global)
// ---------------------------------------------------------------------------
__global__ void __launch_bounds__(NTHREADS, 2)
k_moe_gemm(const int* __restrict__ splits, float* __restrict__ out) {
    extern __shared__ char smem[];
    uint32_t sbase = smem_to_u32(smem);
    volatile int* s_next = (volatile int*)(smem + NSTAGE * STAGE);
    int tid = threadIdx.x;
    int wid = tid >> 5;
    int lid = tid & 31;
    int wm = wid >> 1;        // 0..1  (64-row slab)
    int wn = wid & 1;         // 0..1  (64-col slab)

    // A lanes: tile groups {r0-7,k0},{r8-15,k0},{r0-7,k1},{r8-15,k1}
    int rA = wm * 64 + (lid & 15);          // + mi*16
    int cA = lid >> 4;                      // 16B-chunk, + 2*ks
    int sA = lid & 7;                       // swizzle term (row & 7)
    // B lanes: tile groups {n0-7,k0},{n0-7,k1},{n8-15,k0},{n8-15,k1}
    int rB = wn * 64 + (lid & 7) + ((lid >> 4) & 1) * 8;   // + bp*16
    int cB = (lid >> 3) & 1;                // + 2*ks
    int sB = lid & 7;
    uint32_t baseA = (uint32_t)rA * 128;
    uint32_t baseB = (uint32_t)rB * 128;

    if (tid == 0) s_next[0] = atomicAdd(&d_tilectr, 1);
    __syncthreads();
    int cur = s_next[0];
    if (cur >= NTILES) return;
    int m0 = (cur / NTN) * TILE_M;
    int n0 = (cur % NTN) * TILE_N;
    int e  = expert_of(splits, m0);

    float acc[4][8][4];
    #pragma unroll
    for (int mi = 0; mi < 4; mi++)
        #pragma unroll
        for (int ni = 0; ni < 8; ni++)
            #pragma unroll
            for (int q = 0; q < 4; q++) acc[mi][ni][q] = 0.f;

    uint32_t st_c = sbase, st_n = sbase + STAGE, st_p = sbase + 2 * STAGE;
    load_chunk_half(st_c, 0, tid, m0, n0, e, 0);
    load_chunk_half(st_c, 0, tid, m0, n0, e, 1); cp_commit();
    load_chunk_half(st_n, 1, tid, m0, n0, e, 0);
    load_chunk_half(st_n, 1, tid, m0, n0, e, 1); cp_commit();

    int nxt = NTILES, nm0 = 0, nn0 = 0, ne = 0;
    while (true) {
        for (int ch = 0; ch < NUM_CH; ch++) {
            cp_wait<1>();
            __syncthreads();  // all warps done with slot st_p -> safe to refill
            if (ch == 14) {
                nxt = s_next[0];
                if (nxt < NTILES) {
                    nm0 = (nxt / NTN) * TILE_M;
                    nn0 = (nxt % NTN) * TILE_N;
                    ne  = expert_of(splits, nm0);
                }
            }
            // prefetch target for this chunk (2-chunk slack in the ring)
            bool pref_cur = (ch < NUM_CH - 2);
            bool pref = pref_cur || (nxt < NTILES);
            int  pch  = pref_cur ? ch + 2 : ch - (NUM_CH - 2);
            int  pm0  = pref_cur ? m0 : nm0;
            int  pn0  = pref_cur ? n0 : nn0;
            int  pe   = pref_cur ? e  : ne;

            uint32_t A = st_c, B = st_c + TBYTES;

            #pragma unroll
            for (int ks = 0; ks < 4; ks++) {   // 4 k8-steps per 32-K chunk
                uint32_t coA = (uint32_t)(((cA + 2 * ks) ^ sA) << 4);
                uint32_t coB = (uint32_t)(((cB + 2 * ks) ^ sB) << 4);
                uint32_t a[4][4], b[4][4];
                #pragma unroll
                for (int mi = 0; mi < 4; mi++)
                    ldm_x4(a[mi], A + baseA + mi * 2048 + coA);
                #pragma unroll
                for (int bp = 0; bp < 4; bp++)
                    ldm_x4(b[bp], B + baseB + bp * 2048 + coB);
                // interleave prefetch AFTER fragment loads: tensor pipe is
                // already fed; LDGSTS issue hides under the mma burst
                if (ks < 2 && pref)
                    load_chunk_half(st_p, pch, tid, pm0, pn0, pe, ks);
                if (ks == 1) cp_commit();   // exactly one commit per chunk
                // b[bp]: regs 0,1 = n-rows bp*16+0-7; regs 2,3 = +8-15
                #pragma unroll
                for (int mi = 0; mi < 4; mi++)
                    #pragma unroll
                    for (int ni = 0; ni < 8; ni++)
                        mma_tf32(acc[mi][ni], a[mi], &b[ni >> 1][(ni & 1) * 2]);
            }
            if (ch == 13 && tid == 0) s_next[0] = atomicAdd(&d_tilectr, 1);
            uint32_t tmp = st_c; st_c = st_n; st_n = st_p; st_p = tmp;
        }

        // fused epilogue: out[inv[m]] += acc * rowscale[m]  (scatter-reduce)
        {
            int r0 = m0 + wm * 64 + (lid >> 2);
            int ncol0 = n0 + wn * 64 + (lid & 3) * 2;
            #pragma unroll
            for (int mi = 0; mi < 4; mi++) {
                int ma = r0 + mi * 16, mb = ma + 8;
                int   ta = d_inv[ma],      tb = d_inv[mb];
                float sa = d_rowscale[ma], sb = d_rowscale[mb];
                #pragma unroll
                for (int ni = 0; ni < 8; ni++) {
                    int n = ncol0 + ni * 8;
                    red_add_v2(&out[(size_t)ta * NDIM + n],
                               acc[mi][ni][0] * sa, acc[mi][ni][1] * sa);
                    red_add_v2(&out[(size_t)tb * NDIM + n],
                               acc[mi][ni][2] * sb, acc[mi][ni][3] * sb);
                }
            }
        }

        if (nxt >= NTILES) break;
        cur = nxt; m0 = nm0; n0 = nn0; e = ne;
        #pragma unroll
        for (int mi = 0; mi < 4; mi++)
            #pragma unroll
            for (int ni = 0; ni < 8; ni++)
                #pragma unroll
                for (int q = 0; q < 4; q++) acc[mi][ni][q] = 0.f;
    }
    cp_wait<0>();   // drain in-flight groups before exit
}

extern "C" void kernel_launch(void* const* d_in, const int* in_sizes, int n_in,
                              void* d_out, int out_size) {
    const float* inp    = (const float*)d_in[0];
    const float* weight = (const float*)d_in[1];
    const int*   splits = (const int*)d_in[2];
    const int*   sidx   = (const int*)d_in[3];
    const float* iscale = (const float*)d_in[4];
    const float* wscale = (const float*)d_in[5];
    const float* ovs    = (const float*)d_in[6];
    float* out = (float*)d_out;

    cudaFuncSetAttribute(k_moe_gemm,
                         cudaFuncAttributeMaxDynamicSharedMemorySize, SMEM_GEMM);

    k_split_input<<<(MROWS * KDIM / 8) / 256, 256>>>((const float4*)inp,
                                                     (float4*)out);
    k_split_weight<<<dim3(KDIM / 32, NDIM / 32, NEXP), dim3(32, 8)>>>(weight);
    k_small<<<(MROWS + 255) / 256, 256>>>(splits, sidx, iscale, wscale, ovs);
    k_moe_gemm<<<GRID_GEMM, NTHREADS, SMEM_GEMM>>>(splits, out);
}

// round 11
// speedup vs baseline: 1.2140x; 1.2140x over previous
#include <cuda_runtime.h>
#include <cuda_bf16.h>
#include <cstdint>

#define NTOK 8192
#define TOPK 2
#define NEXP 8
#define KDIM 512
#define NDIM 1024
#define MROWS (NTOK * TOPK)

#define TILE_M 128
#define TILE_N 128
#define CH_K   32
#define NUM_CH (KDIM / CH_K)
#define NTILES ((MROWS / TILE_M) * (NDIM / TILE_N))
#define NTN    (NDIM / TILE_N)
#define TBYTES (TILE_M * 128)
#define STAGE  (2 * TBYTES)
#define NSTAGE 3
#define SMEM_GEMM (NSTAGE * STAGE + 16)
#define GRID_GEMM 296
#define NTHREADS 128

// prep kernel block ranges
#define PREP_WB 4096                    // weight transpose blocks (16 x 32 x 8)
#define PREP_ZB 4096                    // output-zero blocks (x512 float4 each)
#define PREP_SB 64                      // rowscale/inv blocks
#define PREP_BLOCKS (PREP_WB + PREP_ZB + PREP_SB)

__device__ __forceinline__ uint32_t smem_to_u32(const void* p) {
    uint32_t a;
    asm("{ .reg .u64 t; cvta.to.shared.u64 t, %1; cvt.u32.u64 %0, t; }"
        : "=r"(a) : "l"(p));
    return a;
}
__device__ __forceinline__ void cp_async16(uint32_t dst, const void* src) {
    asm volatile("cp.async.cg.shared.global [%0], [%1], 16;"
                 :: "r"(dst), "l"(src) : "memory");
}
__device__ __forceinline__ void cp_commit() {
    asm volatile("cp.async.commit_group;" ::: "memory");
}
template <int N>
__device__ __forceinline__ void cp_wait() {
    asm volatile("cp.async.wait_group %0;" :: "n"(N) : "memory");
}
__device__ __forceinline__ void ldm_x4(uint32_t* r, uint32_t addr) {
    asm volatile("ldmatrix.sync.aligned.m8n8.x4.shared.b16 {%0,%1,%2,%3}, [%4];"
                 : "=r"(r[0]), "=r"(r[1]), "=r"(r[2]), "=r"(r[3])
                 : "r"(addr));
}
__device__ __forceinline__ void mma_tf32(float* c, const uint32_t* a,
                                         const uint32_t* b) {
    asm volatile(
        "mma.sync.aligned.m16n8k8.row.col.f32.tf32.tf32.f32 "
        "{%0,%1,%2,%3}, {%4,%5,%6,%7}, {%8,%9}, {%0,%1,%2,%3};"
        : "+f"(c[0]), "+f"(c[1]), "+f"(c[2]), "+f"(c[3])
        : "r"(a[0]), "r"(a[1]), "r"(a[2]), "r"(a[3]), "r"(b[0]), "r"(b[1]));
}
__device__ __forceinline__ uint32_t f32_to_tf32(float f) {
    uint32_t o;
    asm("cvt.rna.tf32.f32 %0, %1;" : "=r"(o) : "f"(f));
    return o;
}
__device__ __forceinline__ void red_add_v2(float* gaddr, float x, float y) {
    asm volatile("red.global.add.v2.f32 [%0], {%1, %2};"
                 :: "l"(gaddr), "f"(x), "f"(y) : "memory");
}

// Scratch (A is read directly from the harness input as raw f32 -> HMMA
// truncates to tf32 in the operand read; only the weight needs a transposed
// tf32 copy).
__device__ uint4  d_w_t4[NEXP * NDIM * KDIM / 4];     // tf32 [E,N,K] (32 MB)
__device__ float  d_rowscale[MROWS];
__device__ int    d_inv[MROWS];
__device__ int    d_tilectr;

// ---------------------------------------------------------------------------
// Kernel 1 (fused prep): weight [E,K,N] f32 -> [E,N,K] tf32 transpose;
// zero the output surface; rowscale + inverse scatter + counter reset.
// ---------------------------------------------------------------------------
__global__ void k_prep(const float* __restrict__ w,
                       float4* __restrict__ out4,
                       const int* __restrict__ splits,
                       const int* __restrict__ sidx,
                       const float* __restrict__ is,
                       const float* __restrict__ ws,
                       const float* __restrict__ ovs) {
    __shared__ float tile[32][33];
    int b = blockIdx.x;
    int tid = threadIdx.x;

    if (b < PREP_WB) {
        // weight transpose + tf32 cvt (32x32 tile via SMEM)
        int e  = b >> 9;
        int n0 = ((b >> 4) & 31) * 32;
        int k0 = (b & 15) * 32;
        int tx = tid & 31, ty = tid >> 5;   // (32, 8)
        #pragma unroll
        for (int i = 0; i < 4; i++) {
            int k = k0 + ty + 8 * i;
            tile[ty + 8 * i][tx] = w[((size_t)e * KDIM + k) * NDIM + n0 + tx];
        }
        __syncthreads();
        uint32_t* wt = (uint32_t*)d_w_t4;
        #pragma unroll
        for (int i = 0; i < 4; i++) {
            int n = n0 + ty + 8 * i;
            float v = tile[tx][ty + 8 * i];   // = w[e][k0+tx][n]
            size_t o = ((size_t)e * NDIM + n) * KDIM + k0 + tx;
            wt[o] = f32_to_tf32(v);
        }
    } else if (b < PREP_WB + PREP_ZB) {
        // zero output: 512 float4 per block (2 per thread)
        int i = (b - PREP_WB) * 512 + tid * 2;
        out4[i]     = make_float4(0.f, 0.f, 0.f, 0.f);
        out4[i + 1] = make_float4(0.f, 0.f, 0.f, 0.f);
    } else {
        // rowscale + inverse scatter index + tile counter reset
        int m = (b - PREP_WB - PREP_ZB) * 256 + tid;
        if (m == 0) d_tilectr = 0;
        if (m < MROWS) {
            int e = 0, cum = splits[0];
            while (m >= cum && e < NEXP - 1) { e++; cum += splits[e]; }
            d_rowscale[m] = is[0] * ws[e] * ovs[m];
            d_inv[sidx[m]] = m / TOPK;
        }
    }
}

__device__ __forceinline__ int expert_of(const int* splits, int m0) {
    int e = 0, cum = splits[0];
    while (m0 >= cum && e < NEXP - 1) { e++; cum += splits[e]; }
    return e;
}

__device__ __forceinline__ void load_chunk(uint32_t stagebase, int ch,
                                           int tid, int m0, int n0, int e,
                                           const char* aT) {
    const char* bT = (const char*)d_w_t4;
    // 1024 16B-chunks per tensor: row = i>>3 (128 rows), c = i&7 (8 x 16B)
    #pragma unroll
    for (int rep = 0; rep < 8; rep++) {
        int i = tid + rep * NTHREADS;
        int row = i >> 3, c = i & 7;
        uint32_t soff = row * 128 + ((c ^ (row & 7)) << 4);
        size_t ga = ((size_t)(m0 + row) * KDIM + ch * CH_K) * 4 + c * 16;
        size_t gb = (((size_t)e * NDIM + n0 + row) * KDIM + ch * CH_K) * 4 + c * 16;
        cp_async16(stagebase + soff, aT + ga);
        cp_async16(stagebase + TBYTES + soff, bT + gb);
    }
}

// ---------------------------------------------------------------------------
// Kernel 2: persistent grouped GEMM (single-pass tf32 mma m16n8k8, A read
// directly from f32 input with HW truncation, 64x64 warp tiles, 3-stage
// cp.async ring rolling across tile boundaries, dynamic tile stealing,
// fused scale + scatter-reduce epilogue via red.global)  [R9 body verbatim]
// ---------------------------------------------------------------------------
__global__ void __launch_bounds__(NTHREADS, 2)
k_moe_gemm(const int* __restrict__ splits, const float* __restrict__ inp,
           float* __restrict__ out) {
    extern __shared__ char smem[];
    uint32_t sbase = smem_to_u32(smem);
    volatile int* s_next = (volatile int*)(smem + NSTAGE * STAGE);
    const char* aT = (const char*)inp;
    int tid = threadIdx.x;
    int wid = tid >> 5;
    int lid = tid & 31;
    int wm = wid >> 1;        // 0..1  (64-row slab)
    int wn = wid & 1;         // 0..1  (64-col slab)

    // A lanes: tile groups {r0-7,k0},{r8-15,k0},{r0-7,k1},{r8-15,k1}
    int rA = wm * 64 + (lid & 15);          // + mi*16
    int cA = lid >> 4;                      // 16B-chunk, + 2*ks
    int sA = lid & 7;                       // swizzle term (row & 7)
    // B lanes: tile groups {n0-7,k0},{n0-7,k1},{n8-15,k0},{n8-15,k1}
    int rB = wn * 64 + (lid & 7) + ((lid >> 4) & 1) * 8;   // + bp*16
    int cB = (lid >> 3) & 1;                // + 2*ks
    int sB = lid & 7;
    uint32_t baseA = (uint32_t)rA * 128;
    uint32_t baseB = (uint32_t)rB * 128;

    if (tid == 0) s_next[0] = atomicAdd(&d_tilectr, 1);
    __syncthreads();
    int cur = s_next[0];
    if (cur >= NTILES) return;
    int m0 = (cur / NTN) * TILE_M;
    int n0 = (cur % NTN) * TILE_N;
    int e  = expert_of(splits, m0);

    float acc[4][8][4];
    #pragma unroll
    for (int mi = 0; mi < 4; mi++)
        #pragma unroll
        for (int ni = 0; ni < 8; ni++)
            #pragma unroll
            for (int q = 0; q < 4; q++) acc[mi][ni][q] = 0.f;

    uint32_t st_c = sbase, st_n = sbase + STAGE, st_p = sbase + 2 * STAGE;
    load_chunk(st_c, 0, tid, m0, n0, e, aT); cp_commit();
    load_chunk(st_n, 1, tid, m0, n0, e, aT); cp_commit();

    int nxt = NTILES, nm0 = 0, nn0 = 0, ne = 0;
    while (true) {
        for (int ch = 0; ch < NUM_CH; ch++) {
            cp_wait<1>();
            __syncthreads();  // all warps done with slot st_p -> safe to refill
            if (ch == 14) {
                nxt = s_next[0];
                if (nxt < NTILES) {
                    nm0 = (nxt / NTN) * TILE_M;
                    nn0 = (nxt % NTN) * TILE_N;
                    ne  = expert_of(splits, nm0);
                }
            }
            if (ch < NUM_CH - 2) {
                load_chunk(st_p, ch + 2, tid, m0, n0, e, aT);
            } else if (nxt < NTILES) {
                load_chunk(st_p, ch - (NUM_CH - 2), tid, nm0, nn0, ne, aT);
            }
            cp_commit();
            if (ch == 13 && tid == 0) s_next[0] = atomicAdd(&d_tilectr, 1);

            uint32_t A = st_c, B = st_c + TBYTES;

            #pragma unroll
            for (int ks = 0; ks < 4; ks++) {   // 4 k8-steps per 32-K chunk
                uint32_t coA = (uint32_t)(((cA + 2 * ks) ^ sA) << 4);
                uint32_t coB = (uint32_t)(((cB + 2 * ks) ^ sB) << 4);
                uint32_t a[4][4], b[4][4];
                #pragma unroll
                for (int mi = 0; mi < 4; mi++)
                    ldm_x4(a[mi], A + baseA + mi * 2048 + coA);
                #pragma unroll
                for (int bp = 0; bp < 4; bp++)
                    ldm_x4(b[bp], B + baseB + bp * 2048 + coB);
                // b[bp]: regs 0,1 = n-rows bp*16+0-7; regs 2,3 = +8-15
                #pragma unroll
                for (int mi = 0; mi < 4; mi++)
                    #pragma unroll
                    for (int ni = 0; ni < 8; ni++)
                        mma_tf32(acc[mi][ni], a[mi], &b[ni >> 1][(ni & 1) * 2]);
            }
            uint32_t tmp = st_c; st_c = st_n; st_n = st_p; st_p = tmp;
        }

        // fused epilogue: out[inv[m]] += acc * rowscale[m]  (scatter-reduce)
        {
            int r0 = m0 + wm * 64 + (lid >> 2);
            int ncol0 = n0 + wn * 64 + (lid & 3) * 2;
            #pragma unroll
            for (int mi = 0; mi < 4; mi++) {
                int ma = r0 + mi * 16, mb = ma + 8;
                int   ta = d_inv[ma],      tb = d_inv[mb];
                float sa = d_rowscale[ma], sb = d_rowscale[mb];
                #pragma unroll
                for (int ni = 0; ni < 8; ni++) {
                    int n = ncol0 + ni * 8;
                    red_add_v2(&out[(size_t)ta * NDIM + n],
                               acc[mi][ni][0] * sa, acc[mi][ni][1] * sa);
                    red_add_v2(&out[(size_t)tb * NDIM + n],
                               acc[mi][ni][2] * sb, acc[mi][ni][3] * sb);
                }
            }
        }

        if (nxt >= NTILES) break;
        cur = nxt; m0 = nm0; n0 = nn0; e = ne;
        #pragma unroll
        for (int mi = 0; mi < 4; mi++)
            #pragma unroll
            for (int ni = 0; ni < 8; ni++)
                #pragma unroll
                for (int q = 0; q < 4; q++) acc[mi][ni][q] = 0.f;
    }
    cp_wait<0>();   // drain in-flight groups before exit
}

extern "C" void kernel_launch(void* const* d_in, const int* in_sizes, int n_in,
                              void* d_out, int out_size) {
    const float* inp    = (const float*)d_in[0];
    const float* weight = (const float*)d_in[1];
    const int*   splits = (const int*)d_in[2];
    const int*   sidx   = (const int*)d_in[3];
    const float* iscale = (const float*)d_in[4];
    const float* wscale = (const float*)d_in[5];
    const float* ovs    = (const float*)d_in[6];
    float* out = (float*)d_out;

    cudaFuncSetAttribute(k_moe_gemm,
                         cudaFuncAttributeMaxDynamicSharedMemorySize, SMEM_GEMM);

    k_prep<<<PREP_BLOCKS, 256>>>(weight, (float4*)out, splits, sidx,
                                 iscale, wscale, ovs);
    k_moe_gemm<<<GRID_GEMM, NTHREADS, SMEM_GEMM>>>(splits, inp, out);
}

// round 12
// speedup vs baseline: 1.7357x; 1.4297x over previous
#include <cuda_runtime.h>
#include <cuda_fp16.h>
#include <cstdint>

#define NTOK 8192
#define TOPK 2
#define NEXP 8
#define KDIM 512
#define NDIM 1024
#define MROWS (NTOK * TOPK)

#define TILE_M 128
#define TILE_N 128
#define CH_K   64                          // fp16 K elems per chunk (128 B/row)
#define NUM_CH (KDIM / CH_K)               // 8
#define NTILES ((MROWS / TILE_M) * (NDIM / TILE_N))
#define NTN    (NDIM / TILE_N)
#define TBYTES (TILE_M * 128)              // 16384 per tensor
#define STAGE  (2 * TBYTES)                // A + B = 32768
#define NSTAGE 3
#define SMEM_GEMM (NSTAGE * STAGE + 16)
#define GRID_GEMM 296
#define NTHREADS 128

// prep kernel block ranges
#define PREP_WB 4096                       // weight transpose (8E x 32n0 x 16k0)
#define PREP_AB 4096                       // input f32->fp16 cvt
#define PREP_ZB 4096                       // output zero
#define PREP_SB 64                         // rowscale/inv
#define PREP_BLOCKS (PREP_WB + PREP_AB + PREP_ZB + PREP_SB)

__device__ __forceinline__ uint32_t smem_to_u32(const void* p) {
    uint32_t a;
    asm("{ .reg .u64 t; cvta.to.shared.u64 t, %1; cvt.u32.u64 %0, t; }"
        : "=r"(a) : "l"(p));
    return a;
}
__device__ __forceinline__ void cp_async16(uint32_t dst, const void* src) {
    asm volatile("cp.async.cg.shared.global [%0], [%1], 16;"
                 :: "r"(dst), "l"(src) : "memory");
}
__device__ __forceinline__ void cp_commit() {
    asm volatile("cp.async.commit_group;" ::: "memory");
}
template <int N>
__device__ __forceinline__ void cp_wait() {
    asm volatile("cp.async.wait_group %0;" :: "n"(N) : "memory");
}
__device__ __forceinline__ void ldm_x4(uint32_t* r, uint32_t addr) {
    asm volatile("ldmatrix.sync.aligned.m8n8.x4.shared.b16 {%0,%1,%2,%3}, [%4];"
                 : "=r"(r[0]), "=r"(r[1]), "=r"(r[2]), "=r"(r[3])
                 : "r"(addr));
}
__device__ __forceinline__ void mma_f16(float* c, const uint32_t* a,
                                        const uint32_t* b) {
    asm volatile(
        "mma.sync.aligned.m16n8k16.row.col.f32.f16.f16.f32 "
        "{%0,%1,%2,%3}, {%4,%5,%6,%7}, {%8,%9}, {%0,%1,%2,%3};"
        : "+f"(c[0]), "+f"(c[1]), "+f"(c[2]), "+f"(c[3])
        : "r"(a[0]), "r"(a[1]), "r"(a[2]), "r"(a[3]), "r"(b[0]), "r"(b[1]));
}
__device__ __forceinline__ void red_add_v2(float* gaddr, float x, float y) {
    asm volatile("red.global.add.v2.f32 [%0], {%1, %2};"
                 :: "l"(gaddr), "f"(x), "f"(y) : "memory");
}

// Scratch (static __device__ — no allocation allowed)
__device__ uint4  d_a_h4[MROWS * KDIM / 8];           // fp16 [M,K]   (16 MB)
__device__ uint4  d_w_h4[NEXP * NDIM * KDIM / 8];     // fp16 [E,N,K] (16 MB)
__device__ float  d_rowscale[MROWS];
__device__ int    d_inv[MROWS];
__device__ int    d_tilectr;

// ---------------------------------------------------------------------------
// Kernel 1 (fused prep): weight transpose+cvt, input cvt, zero output,
// rowscale + inverse scatter + counter reset — partitioned by blockIdx.
// ---------------------------------------------------------------------------
__global__ void k_prep(const float* __restrict__ w,
                       const float4* __restrict__ in4,
                       float4* __restrict__ out4,
                       const int* __restrict__ splits,
                       const int* __restrict__ sidx,
                       const float* __restrict__ is,
                       const float* __restrict__ ws,
                       const float* __restrict__ ovs) {
    __shared__ float tile[32][33];
    int b = blockIdx.x;
    int tid = threadIdx.x;

    if (b < PREP_WB) {
        // weight [E,K,N] f32 -> [E,N,K] fp16 (32x32 tile via SMEM)
        int e  = b >> 9;
        int n0 = ((b >> 4) & 31) * 32;
        int k0 = (b & 15) * 32;
        int tx = tid & 31, ty = tid >> 5;   // (32, 8)
        #pragma unroll
        for (int i = 0; i < 4; i++) {
            int k = k0 + ty + 8 * i;
            tile[ty + 8 * i][tx] = w[((size_t)e * KDIM + k) * NDIM + n0 + tx];
        }
        __syncthreads();
        __half* wh = (__half*)d_w_h4;
        #pragma unroll
        for (int i = 0; i < 4; i++) {
            int n = n0 + ty + 8 * i;
            float v = tile[tx][ty + 8 * i];   // = w[e][k0+tx][n]
            size_t o = ((size_t)e * NDIM + n) * KDIM + k0 + tx;
            wh[o] = __float2half_rn(v);
        }
    } else if (b < PREP_WB + PREP_AB) {
        // input f32 -> fp16 (8 elems/thread)
        int i = (b - PREP_WB) * 256 + tid;    // uint4 (8 fp16) index
        float4 v0 = in4[2 * i], v1 = in4[2 * i + 1];
        __half2 h0 = __float22half2_rn(make_float2(v0.x, v0.y));
        __half2 h1 = __float22half2_rn(make_float2(v0.z, v0.w));
        __half2 h2 = __float22half2_rn(make_float2(v1.x, v1.y));
        __half2 h3 = __float22half2_rn(make_float2(v1.z, v1.w));
        uint4 u;
        u.x = *(uint32_t*)&h0; u.y = *(uint32_t*)&h1;
        u.z = *(uint32_t*)&h2; u.w = *(uint32_t*)&h3;
        d_a_h4[i] = u;
    } else if (b < PREP_WB + PREP_AB + PREP_ZB) {
        // zero output: 512 float4 per block (2 per thread)
        int i = (b - PREP_WB - PREP_AB) * 512 + tid * 2;
        out4[i]     = make_float4(0.f, 0.f, 0.f, 0.f);
        out4[i + 1] = make_float4(0.f, 0.f, 0.f, 0.f);
    } else {
        // rowscale + inverse scatter index + tile counter reset
        int m = (b - PREP_WB - PREP_AB - PREP_ZB) * 256 + tid;
        if (m == 0) d_tilectr = 0;
        if (m < MROWS) {
            int e = 0, cum = splits[0];
            while (m >= cum && e < NEXP - 1) { e++; cum += splits[e]; }
            d_rowscale[m] = is[0] * ws[e] * ovs[m];
            d_inv[sidx[m]] = m / TOPK;
        }
    }
}

__device__ __forceinline__ int expert_of(const int* splits, int m0) {
    int e = 0, cum = splits[0];
    while (m0 >= cum && e < NEXP - 1) { e++; cum += splits[e]; }
    return e;
}

__device__ __forceinline__ void load_chunk(uint32_t stagebase, int ch,
                                           int tid, int m0, int n0, int e) {
    const char* aT = (const char*)d_a_h4;
    const char* bT = (const char*)d_w_h4;
    // 1024 16B-chunks per tensor: row = i>>3 (128 rows), c = i&7 (8 x 16B)
    #pragma unroll
    for (int rep = 0; rep < 8; rep++) {
        int i = tid + rep * NTHREADS;
        int row = i >> 3, c = i & 7;
        uint32_t soff = row * 128 + ((c ^ (row & 7)) << 4);
        size_t ga = ((size_t)(m0 + row) * KDIM + ch * CH_K) * 2 + c * 16;
        size_t gb = (((size_t)e * NDIM + n0 + row) * KDIM + ch * CH_K) * 2 + c * 16;
        cp_async16(stagebase + soff, aT + ga);
        cp_async16(stagebase + TBYTES + soff, bT + gb);
    }
}

// ---------------------------------------------------------------------------
// Kernel 2: persistent grouped GEMM (single-pass fp16 mma m16n8k16, 64x64
// warp tiles, 3-stage cp.async ring rolling across tile boundaries, dynamic
// tile stealing, fused scale + scatter-reduce epilogue via red.global)
// ---------------------------------------------------------------------------
__global__ void __launch_bounds__(NTHREADS, 2)
k_moe_gemm(const int* __restrict__ splits, float* __restrict__ out) {
    extern __shared__ char smem[];
    uint32_t sbase = smem_to_u32(smem);
    volatile int* s_next = (volatile int*)(smem + NSTAGE * STAGE);
    int tid = threadIdx.x;
    int wid = tid >> 5;
    int lid = tid & 31;
    int wm = wid >> 1;        // 0..1  (64-row slab)
    int wn = wid & 1;         // 0..1  (64-col slab)

    // A lanes (m16n8k16): x4 tiles {r0-7,c0},{r8-15,c0},{r0-7,c1},{r8-15,c1}
    // where c = 16B chunk (8 fp16 = k8); k16 step spans chunks 2*ks, 2*ks+1
    int rA = wm * 64 + (lid & 15);          // + mi*16
    int cA = lid >> 4;                      // + 2*ks
    int sA = lid & 7;                       // swizzle term (row & 7)
    // B lanes: x4 tiles {n0-7,c0},{n0-7,c1},{n8-15,c0},{n8-15,c1}
    int rB = wn * 64 + (lid & 7) + ((lid >> 4) & 1) * 8;   // + bp*16
    int cB = (lid >> 3) & 1;                // + 2*ks
    int sB = lid & 7;
    uint32_t baseA = (uint32_t)rA * 128;
    uint32_t baseB = (uint32_t)rB * 128;

    if (tid == 0) s_next[0] = atomicAdd(&d_tilectr, 1);
    __syncthreads();
    int cur = s_next[0];
    if (cur >= NTILES) return;
    int m0 = (cur / NTN) * TILE_M;
    int n0 = (cur % NTN) * TILE_N;
    int e  = expert_of(splits, m0);

    float acc[4][8][4];
    #pragma unroll
    for (int mi = 0; mi < 4; mi++)
        #pragma unroll
        for (int ni = 0; ni < 8; ni++)
            #pragma unroll
            for (int q = 0; q < 4; q++) acc[mi][ni][q] = 0.f;

    uint32_t st_c = sbase, st_n = sbase + STAGE, st_p = sbase + 2 * STAGE;
    load_chunk(st_c, 0, tid, m0, n0, e); cp_commit();
    load_chunk(st_n, 1, tid, m0, n0, e); cp_commit();

    int nxt = NTILES, nm0 = 0, nn0 = 0, ne = 0;
    while (true) {
        for (int ch = 0; ch < NUM_CH; ch++) {
            cp_wait<1>();
            __syncthreads();  // all warps done with slot st_p -> safe to refill
            if (ch == NUM_CH - 2) {          // read next tile (published ch-1)
                nxt = s_next[0];
                if (nxt < NTILES) {
                    nm0 = (nxt / NTN) * TILE_M;
                    nn0 = (nxt % NTN) * TILE_N;
                    ne  = expert_of(splits, nm0);
                }
            }
            if (ch < NUM_CH - 2) {
                load_chunk(st_p, ch + 2, tid, m0, n0, e);
            } else if (nxt < NTILES) {
                load_chunk(st_p, ch - (NUM_CH - 2), tid, nm0, nn0, ne);
            }
            cp_commit();
            if (ch == NUM_CH - 3 && tid == 0)
                s_next[0] = atomicAdd(&d_tilectr, 1);

            uint32_t A = st_c, B = st_c + TBYTES;

            #pragma unroll
            for (int ks = 0; ks < 4; ks++) {   // 4 k16-steps per 64-K chunk
                uint32_t coA = (uint32_t)(((cA + 2 * ks) ^ sA) << 4);
                uint32_t coB = (uint32_t)(((cB + 2 * ks) ^ sB) << 4);
                uint32_t a[4][4], b[4][4];
                #pragma unroll
                for (int mi = 0; mi < 4; mi++)
                    ldm_x4(a[mi], A + baseA + mi * 2048 + coA);
                #pragma unroll
                for (int bp = 0; bp < 4; bp++)
                    ldm_x4(b[bp], B + baseB + bp * 2048 + coB);
                // b[bp]: regs 0,1 = n-rows bp*16+0-7 (k0-7, k8-15);
                //        regs 2,3 = n-rows bp*16+8-15
                #pragma unroll
                for (int mi = 0; mi < 4; mi++)
                    #pragma unroll
                    for (int ni = 0; ni < 8; ni++)
                        mma_f16(acc[mi][ni], a[mi], &b[ni >> 1][(ni & 1) * 2]);
            }
            uint32_t tmp = st_c; st_c = st_n; st_n = st_p; st_p = tmp;
        }

        // fused epilogue: out[inv[m]] += acc * rowscale[m]  (scatter-reduce)
        {
            int r0 = m0 + wm * 64 + (lid >> 2);
            int ncol0 = n0 + wn * 64 + (lid & 3) * 2;
            #pragma unroll
            for (int mi = 0; mi < 4; mi++) {
                int ma = r0 + mi * 16, mb = ma + 8;
                int   ta = d_inv[ma],      tb = d_inv[mb];
                float sa = d_rowscale[ma], sb = d_rowscale[mb];
                #pragma unroll
                for (int ni = 0; ni < 8; ni++) {
                    int n = ncol0 + ni * 8;
                    red_add_v2(&out[(size_t)ta * NDIM + n],
                               acc[mi][ni][0] * sa, acc[mi][ni][1] * sa);
                    red_add_v2(&out[(size_t)tb * NDIM + n],
                               acc[mi][ni][2] * sb, acc[mi][ni][3] * sb);
                }
            }
        }

        if (nxt >= NTILES) break;
        cur = nxt; m0 = nm0; n0 = nn0; e = ne;
        #pragma unroll
        for (int mi = 0; mi < 4; mi++)
            #pragma unroll
            for (int ni = 0; ni < 8; ni++)
                #pragma unroll
                for (int q = 0; q < 4; q++) acc[mi][ni][q] = 0.f;
    }
    cp_wait<0>();   // drain in-flight groups before exit
}

extern "C" void kernel_launch(void* const* d_in, const int* in_sizes, int n_in,
                              void* d_out, int out_size) {
    const float* inp    = (const float*)d_in[0];
    const float* weight = (const float*)d_in[1];
    const int*   splits = (const int*)d_in[2];
    const int*   sidx   = (const int*)d_in[3];
    const float* iscale = (const float*)d_in[4];
    const float* wscale = (const float*)d_in[5];
    const float* ovs    = (const float*)d_in[6];
    float* out = (float*)d_out;

    cudaFuncSetAttribute(k_moe_gemm,
                         cudaFuncAttributeMaxDynamicSharedMemorySize, SMEM_GEMM);

    k_prep<<<PREP_BLOCKS, 256>>>(weight, (const float4*)inp, (float4*)out,
                                 splits, sidx, iscale, wscale, ovs);
    k_moe_gemm<<<GRID_GEMM, NTHREADS, SMEM_GEMM>>>(splits, out);
}